// round 15
// baseline (speedup 1.0000x reference)
#include <cuda_runtime.h>
#include <math.h>

#define BATCH 8192
#define W 256
#define NKCH 128
#define KCHUNK (BATCH / NKCH)        // 64
#define NPAIR 3                      // 128x128 tile-pairs: (0,0),(0,1),(1,1)
#define GRID (NPAIR * NKCH)          // 384

// Device scratch (no allocations). All self-resetting across graph replays.
__device__ float g_G[W * W];          // Gram accumulator (zeroed by finalize tail)
__device__ float g_musum[W] = {};     // column sums
__device__ float g_sqsum[W] = {};     // column sum-of-squares (exact diagonal)
__device__ int   g_fin_count = 0;     // completion counter

// ---- helpers ---------------------------------------------------------------
__device__ __forceinline__ unsigned pack_bf16x2(float even, float odd) {
    unsigned r;   // hi = odd-k, lo = even-k (consistent for A and B)
    asm("cvt.rn.bf16x2.f32 %0, %1, %2;" : "=r"(r) : "f"(odd), "f"(even));
    return r;
}
__device__ __forceinline__ void mma_bf16(float* d, const unsigned* a,
                                         unsigned b0, unsigned b1) {
    asm("mma.sync.aligned.m16n8k16.row.col.f32.bf16.bf16.f32 "
        "{%0,%1,%2,%3}, {%4,%5,%6,%7}, {%8,%9}, {%0,%1,%2,%3};"
        : "+f"(d[0]), "+f"(d[1]), "+f"(d[2]), "+f"(d[3])
        : "r"(a[0]), "r"(a[1]), "r"(a[2]), "r"(a[3]), "r"(b0), "r"(b1));
}

// ---------------------------------------------------------------------------
// Fused kernel: Gram via bf16 MMA on 128x128 symmetric tile-pairs, column
// stats fused into diagonal blocks (fp32-exact), last-finishing block runs
// the finalize epilogue and resets all scratch for the next graph replay.
// Grid 384 = 3 pairs x 128 K-chunks; 256 threads = 8 warps, warp tile 32x64.
// ---------------------------------------------------------------------------
__global__ __launch_bounds__(256) void fused_kernel(const float* __restrict__ E,
                                                    float* __restrict__ out) {
    // k-pairs packed as bf16x2: 16 k2-rows per 32-k chunk, pad 136 (conflict-free)
    __shared__ unsigned As2[16][136];
    __shared__ unsigned Bs2[16][136];
    __shared__ float s_sum[128];
    __shared__ float s_sq[128];
    __shared__ float s_mu[W];
    __shared__ float s_sqd[W];
    __shared__ float red[256];
    __shared__ int   is_last;

    const int tid   = threadIdx.x;
    const int pair  = blockIdx.x / NKCH;         // 0:(0,0) 1:(0,1) 2:(1,1)
    const int chunk = blockIdx.x % NKCH;
    const int i0 = (pair == 2) ? 128 : 0;
    const int j0 = (pair == 0) ? 0 : 128;
    const int k0 = chunk * KCHUNK;
    const bool diag = (i0 == j0);

    const int w    = tid >> 5;
    const int lane = tid & 31;
    const int gid  = lane >> 2;       // 0..7
    const int tig  = lane & 3;        // 0..3
    const int iw   = (w >> 1) * 32;   // 4 m-bands of 32
    const int jw   = (w & 1) * 64;    // 2 n-bands of 64

    float acc[2][8][4];
    #pragma unroll
    for (int m = 0; m < 2; ++m)
        #pragma unroll
        for (int n = 0; n < 8; ++n)
            #pragma unroll
            for (int c = 0; c < 4; ++c) acc[m][n][c] = 0.0f;

    float4 csum = make_float4(0.f, 0.f, 0.f, 0.f);
    float4 csq  = make_float4(0.f, 0.f, 0.f, 0.f);
    if (tid < 128) { s_sum[tid] = 0.0f; s_sq[tid] = 0.0f; }

    const int f  = tid & 31;          // float4 col index (128 cols = 32 float4)
    const int rp = tid >> 5;          // 0..7

    for (int kc = 0; kc < KCHUNK; kc += 32) {
        // Stage 32 rows x 128 cols as packed bf16x2 pairs along k.
        #pragma unroll
        for (int q = 0; q < 2; ++q) {
            int k2 = q * 8 + rp;                        // 0..15
            size_t base = (size_t)(k0 + kc + 2 * k2) * W;
            float4 a0 = ((const float4*)(E + base + i0))[f];
            float4 a1 = ((const float4*)(E + base + W + i0))[f];
            uint4 pa = make_uint4(pack_bf16x2(a0.x, a1.x), pack_bf16x2(a0.y, a1.y),
                                  pack_bf16x2(a0.z, a1.z), pack_bf16x2(a0.w, a1.w));
            *(uint4*)&As2[k2][f * 4] = pa;
            if (diag) {
                csum.x += a0.x + a1.x;
                csum.y += a0.y + a1.y;
                csum.z += a0.z + a1.z;
                csum.w += a0.w + a1.w;
                csq.x = fmaf(a0.x, a0.x, fmaf(a1.x, a1.x, csq.x));
                csq.y = fmaf(a0.y, a0.y, fmaf(a1.y, a1.y, csq.y));
                csq.z = fmaf(a0.z, a0.z, fmaf(a1.z, a1.z, csq.z));
                csq.w = fmaf(a0.w, a0.w, fmaf(a1.w, a1.w, csq.w));
            } else {
                float4 b0 = ((const float4*)(E + base + j0))[f];
                float4 b1 = ((const float4*)(E + base + W + j0))[f];
                uint4 pb = make_uint4(pack_bf16x2(b0.x, b1.x), pack_bf16x2(b0.y, b1.y),
                                      pack_bf16x2(b0.z, b1.z), pack_bf16x2(b0.w, b1.w));
                *(uint4*)&Bs2[k2][f * 4] = pb;
            }
        }
        __syncthreads();

        const unsigned (*Bp)[136] = diag ? As2 : Bs2;

        #pragma unroll
        for (int kb2 = 0; kb2 < 16; kb2 += 8) {         // two k16 steps
            unsigned a[2][4];
            #pragma unroll
            for (int m = 0; m < 2; ++m) {
                int mi = iw + m * 16;
                a[m][0] = As2[kb2 + tig    ][mi + gid    ];
                a[m][1] = As2[kb2 + tig    ][mi + gid + 8];
                a[m][2] = As2[kb2 + tig + 4][mi + gid    ];
                a[m][3] = As2[kb2 + tig + 4][mi + gid + 8];
            }
            #pragma unroll
            for (int n = 0; n < 8; ++n) {
                unsigned b0 = Bp[kb2 + tig    ][jw + n * 8 + gid];
                unsigned b1 = Bp[kb2 + tig + 4][jw + n * 8 + gid];
                mma_bf16(acc[0][n], a[0], b0, b1);
                mma_bf16(acc[1][n], a[1], b0, b1);
            }
        }
        __syncthreads();
    }

    // Accumulate tile into g_G.
    #pragma unroll
    for (int m = 0; m < 2; ++m) {
        int gi = i0 + iw + m * 16 + gid;
        #pragma unroll
        for (int n = 0; n < 8; ++n) {
            int gj = j0 + jw + n * 8 + 2 * tig;
            atomicAdd(&g_G[gi * W + gj],           acc[m][n][0]);
            atomicAdd(&g_G[gi * W + gj + 1],       acc[m][n][1]);
            atomicAdd(&g_G[(gi + 8) * W + gj],     acc[m][n][2]);
            atomicAdd(&g_G[(gi + 8) * W + gj + 1], acc[m][n][3]);
        }
    }

    // Diagonal blocks: flush column stats.
    if (diag) {
        atomicAdd(&s_sum[f * 4 + 0], csum.x);
        atomicAdd(&s_sum[f * 4 + 1], csum.y);
        atomicAdd(&s_sum[f * 4 + 2], csum.z);
        atomicAdd(&s_sum[f * 4 + 3], csum.w);
        atomicAdd(&s_sq[f * 4 + 0], csq.x);
        atomicAdd(&s_sq[f * 4 + 1], csq.y);
        atomicAdd(&s_sq[f * 4 + 2], csq.z);
        atomicAdd(&s_sq[f * 4 + 3], csq.w);
        __syncthreads();
        if (tid < 128) {
            atomicAdd(&g_musum[i0 + tid], s_sum[tid]);
            atomicAdd(&g_sqsum[i0 + tid], s_sq[tid]);
        }
    }

    // ---- last-block-done finalize ------------------------------------------
    __threadfence();                       // release all our global writes
    if (tid == 0) {
        int c = atomicAdd(&g_fin_count, 1);
        is_last = (c == GRID - 1);
    }
    __syncthreads();
    if (!is_last) return;
    __threadfence();                       // acquire other blocks' writes

    const float invB = 1.0f / BATCH;
    s_mu[tid]  = g_musum[tid] * invB;
    s_sqd[tid] = g_sqsum[tid];
    __syncthreads();

    float a = 0.0f;
    // Part A: rows 0..127, full 256 cols (tiles (0,0) w=1, (0,1) w=2).
    for (int s = tid; s < 8192; s += 256) {
        float4 v = ((const float4*)g_G)[s];
        int i  = s >> 6;
        int j4 = (s & 63) * 4;
        float mi = s_mu[i];
        float vv[4] = {v.x, v.y, v.z, v.w};
        #pragma unroll
        for (int c = 0; c < 4; ++c) {
            int j = j4 + c;
            if (j != i) {
                float d = vv[c] * invB - mi * s_mu[j];
                a = fmaf((j >= 128 ? 2.0f : 1.0f) * d, d, a);
            }
        }
    }
    // Part B: tile (1,1), rows/cols 128..255, w=1.
    for (int s = tid; s < 4096; s += 256) {
        int i = 128 + (s >> 5);
        int j4 = 128 + (s & 31) * 4;
        float4 v = *(const float4*)&g_G[i * W + j4];
        float mi = s_mu[i];
        float vv[4] = {v.x, v.y, v.z, v.w};
        #pragma unroll
        for (int c = 0; c < 4; ++c) {
            int j = j4 + c;
            if (j != i) {
                float d = vv[c] * invB - mi * s_mu[j];
                a = fmaf(d, d, a);
            }
        }
    }
    // Exact diagonal: thread t handles i = t.
    {
        float d = s_sqd[tid] * invB - s_mu[tid] * s_mu[tid] - 1.0f;
        a = fmaf(d, d, a);
    }

    red[tid] = a;
    __syncthreads();
    #pragma unroll
    for (int st = 128; st > 0; st >>= 1) {
        if (tid < st) red[tid] += red[tid + st];
        __syncthreads();
    }
    if (tid == 0) out[0] = sqrtf(red[0]);

    // Reset scratch for the next graph replay (only written regions).
    float4 z4 = make_float4(0.f, 0.f, 0.f, 0.f);
    for (int s = tid; s < 8192; s += 256) ((float4*)g_G)[s] = z4;
    for (int s = tid; s < 4096; s += 256) {
        int i = 128 + (s >> 5);
        int j4 = 128 + (s & 31) * 4;
        *(float4*)&g_G[i * W + j4] = z4;
    }
    g_musum[tid] = 0.0f;
    g_sqsum[tid] = 0.0f;
    if (tid == 0) g_fin_count = 0;
}

// ---------------------------------------------------------------------------
extern "C" void kernel_launch(void* const* d_in, const int* in_sizes, int n_in,
                              void* d_out, int out_size) {
    const float* E = (const float*)d_in[0];   // [8192, 256] fp32
    float* out = (float*)d_out;

    fused_kernel<<<GRID, 256>>>(E, out);
}

// round 16
// speedup vs baseline: 2.2317x; 2.2317x over previous
#include <cuda_runtime.h>
#include <math.h>

#define BATCH 8192
#define W 256
#define NKCH 64
#define KCHUNK (BATCH / NKCH)        // 128
#define NPAIR 3                      // 128x128 tile-pairs: (0,0),(0,1),(1,1)
#define GRID (NPAIR * NKCH)          // 192

// Device scratch (no allocations). Split Gram buffers are fully overwritten
// each launch (no zeroing needed); counters self-reset in finalize.
__device__ float g_Gs[NKCH][W * W];   // per-chunk Gram partials (16 MB, plain ST)
__device__ float g_musum[W];          // column sums (zero-init .bss, self-reset)
__device__ float g_sqsum[W];          // column sum-of-squares (exact diagonal)
__device__ float g_sumsq;             // ||D||^2 accumulator (self-reset)
__device__ int   g_fin_count;         // completion counter (self-reset)

// ---- helpers ---------------------------------------------------------------
__device__ __forceinline__ unsigned pack_bf16x2(float even, float odd) {
    unsigned r;   // hi = odd-k, lo = even-k (consistent for A and B)
    asm("cvt.rn.bf16x2.f32 %0, %1, %2;" : "=r"(r) : "f"(odd), "f"(even));
    return r;
}
__device__ __forceinline__ void mma_bf16(float* d, const unsigned* a,
                                         unsigned b0, unsigned b1) {
    asm("mma.sync.aligned.m16n8k16.row.col.f32.bf16.bf16.f32 "
        "{%0,%1,%2,%3}, {%4,%5,%6,%7}, {%8,%9}, {%0,%1,%2,%3};"
        : "+f"(d[0]), "+f"(d[1]), "+f"(d[2]), "+f"(d[3])
        : "r"(a[0]), "r"(a[1]), "r"(a[2]), "r"(a[3]), "r"(b0), "r"(b1));
}

// ---------------------------------------------------------------------------
// K1: Gram via bf16 MMA on 128x128 symmetric tile-pairs + fused column stats.
// Grid 192 = 3 pairs x 64 K-chunks; 256 threads = 8 warps, warp tile 32x64.
// Each block STORES its partial tile to g_Gs[chunk] (no atomics).
// ---------------------------------------------------------------------------
__global__ __launch_bounds__(256) void gram_kernel(const float* __restrict__ E) {
    __shared__ unsigned As2[16][136];  // k-pairs packed bf16x2; pad 136 conflict-free
    __shared__ unsigned Bs2[16][136];
    __shared__ float s_sum[128];
    __shared__ float s_sq[128];

    const int tid   = threadIdx.x;
    const int pair  = blockIdx.x / NKCH;         // 0:(0,0) 1:(0,1) 2:(1,1)
    const int chunk = blockIdx.x % NKCH;
    const int i0 = (pair == 2) ? 128 : 0;
    const int j0 = (pair == 0) ? 0 : 128;
    const int k0 = chunk * KCHUNK;
    const bool diag = (i0 == j0);

    const int w    = tid >> 5;
    const int lane = tid & 31;
    const int gid  = lane >> 2;       // 0..7
    const int tig  = lane & 3;        // 0..3
    const int iw   = (w >> 1) * 32;   // 4 m-bands of 32
    const int jw   = (w & 1) * 64;    // 2 n-bands of 64

    float acc[2][8][4];
    #pragma unroll
    for (int m = 0; m < 2; ++m)
        #pragma unroll
        for (int n = 0; n < 8; ++n)
            #pragma unroll
            for (int c = 0; c < 4; ++c) acc[m][n][c] = 0.0f;

    float4 csum = make_float4(0.f, 0.f, 0.f, 0.f);
    float4 csq  = make_float4(0.f, 0.f, 0.f, 0.f);
    if (tid < 128) { s_sum[tid] = 0.0f; s_sq[tid] = 0.0f; }

    const int f  = tid & 31;          // float4 col index (128 cols = 32 float4)
    const int rp = tid >> 5;          // 0..7

    for (int kc = 0; kc < KCHUNK; kc += 32) {
        // Stage 32 rows x 128 cols as packed bf16x2 pairs along k.
        #pragma unroll
        for (int q = 0; q < 2; ++q) {
            int k2 = q * 8 + rp;                        // 0..15
            size_t base = (size_t)(k0 + kc + 2 * k2) * W;
            float4 a0 = ((const float4*)(E + base + i0))[f];
            float4 a1 = ((const float4*)(E + base + W + i0))[f];
            uint4 pa = make_uint4(pack_bf16x2(a0.x, a1.x), pack_bf16x2(a0.y, a1.y),
                                  pack_bf16x2(a0.z, a1.z), pack_bf16x2(a0.w, a1.w));
            *(uint4*)&As2[k2][f * 4] = pa;
            if (diag) {
                csum.x += a0.x + a1.x;
                csum.y += a0.y + a1.y;
                csum.z += a0.z + a1.z;
                csum.w += a0.w + a1.w;
                csq.x = fmaf(a0.x, a0.x, fmaf(a1.x, a1.x, csq.x));
                csq.y = fmaf(a0.y, a0.y, fmaf(a1.y, a1.y, csq.y));
                csq.z = fmaf(a0.z, a0.z, fmaf(a1.z, a1.z, csq.z));
                csq.w = fmaf(a0.w, a0.w, fmaf(a1.w, a1.w, csq.w));
            } else {
                float4 b0 = ((const float4*)(E + base + j0))[f];
                float4 b1 = ((const float4*)(E + base + W + j0))[f];
                uint4 pb = make_uint4(pack_bf16x2(b0.x, b1.x), pack_bf16x2(b0.y, b1.y),
                                      pack_bf16x2(b0.z, b1.z), pack_bf16x2(b0.w, b1.w));
                *(uint4*)&Bs2[k2][f * 4] = pb;
            }
        }
        __syncthreads();

        const unsigned (*Bp)[136] = diag ? As2 : Bs2;

        #pragma unroll
        for (int kb2 = 0; kb2 < 16; kb2 += 8) {         // two k16 steps
            unsigned a[2][4];
            #pragma unroll
            for (int m = 0; m < 2; ++m) {
                int mi = iw + m * 16;
                a[m][0] = As2[kb2 + tig    ][mi + gid    ];
                a[m][1] = As2[kb2 + tig    ][mi + gid + 8];
                a[m][2] = As2[kb2 + tig + 4][mi + gid    ];
                a[m][3] = As2[kb2 + tig + 4][mi + gid + 8];
            }
            #pragma unroll
            for (int n = 0; n < 8; ++n) {
                unsigned b0 = Bp[kb2 + tig    ][jw + n * 8 + gid];
                unsigned b1 = Bp[kb2 + tig + 4][jw + n * 8 + gid];
                mma_bf16(acc[0][n], a[0], b0, b1);
                mma_bf16(acc[1][n], a[1], b0, b1);
            }
        }
        __syncthreads();
    }

    // Plain stores of the partial tile (disjoint addresses; no atomics).
    float* dst = g_Gs[chunk];
    #pragma unroll
    for (int m = 0; m < 2; ++m) {
        int gi = i0 + iw + m * 16 + gid;
        #pragma unroll
        for (int n = 0; n < 8; ++n) {
            int gj = j0 + jw + n * 8 + 2 * tig;
            *(float2*)&dst[gi * W + gj]       = make_float2(acc[m][n][0], acc[m][n][1]);
            *(float2*)&dst[(gi + 8) * W + gj] = make_float2(acc[m][n][2], acc[m][n][3]);
        }
    }

    // Diagonal blocks: flush column stats (tiny atomic traffic).
    if (diag) {
        atomicAdd(&s_sum[f * 4 + 0], csum.x);
        atomicAdd(&s_sum[f * 4 + 1], csum.y);
        atomicAdd(&s_sum[f * 4 + 2], csum.z);
        atomicAdd(&s_sum[f * 4 + 3], csum.w);
        atomicAdd(&s_sq[f * 4 + 0], csq.x);
        atomicAdd(&s_sq[f * 4 + 1], csq.y);
        atomicAdd(&s_sq[f * 4 + 2], csq.z);
        atomicAdd(&s_sq[f * 4 + 3], csq.w);
        __syncthreads();
        if (tid < 128) {
            atomicAdd(&g_musum[i0 + tid], s_sum[tid]);
            atomicAdd(&g_sqsum[i0 + tid], s_sq[tid]);
        }
    }
}

// ---------------------------------------------------------------------------
// K2: finalize. 128 blocks x 256 threads; block b -> rows b and 255-b (upper
// triangle). Sums the 64 chunk splits per entry (L2-resident). Diagonal uses
// exact fp32 sumsq. Last block writes sqrt and resets counters for replay.
// ---------------------------------------------------------------------------
__global__ void finalize_kernel(float* __restrict__ out) {
    __shared__ float mu[W];
    __shared__ float sq[W];
    __shared__ float red[256];
    __shared__ int   is_last;

    const int t = threadIdx.x;
    const float invB = 1.0f / BATCH;
    mu[t] = g_musum[t] * invB;
    sq[t] = g_sqsum[t];
    __syncthreads();

    float acc = 0.0f;
    int rows[2] = {(int)blockIdx.x, (W - 1) - (int)blockIdx.x};
    #pragma unroll
    for (int r = 0; r < 2; ++r) {
        int i = rows[r];
        int j = i + t;                 // upper triangle only
        if (j < W) {
            if (t == 0) {
                float d = sq[i] * invB - mu[i] * mu[i] - 1.0f;  // exact diagonal
                acc += d * d;
            } else {
                // Sum the 64 splits with 4 independent accumulators (MLP).
                float G0 = 0.f, G1 = 0.f, G2 = 0.f, G3 = 0.f;
                int off = i * W + j;
                #pragma unroll
                for (int s = 0; s < NKCH; s += 4) {
                    G0 += g_Gs[s + 0][off];
                    G1 += g_Gs[s + 1][off];
                    G2 += g_Gs[s + 2][off];
                    G3 += g_Gs[s + 3][off];
                }
                float d = ((G0 + G1) + (G2 + G3)) * invB - mu[i] * mu[j];
                acc += 2.0f * d * d;
            }
        }
    }

    red[t] = acc;
    __syncthreads();
    #pragma unroll
    for (int st = 128; st > 0; st >>= 1) {
        if (t < st) red[t] += red[t + st];
        __syncthreads();
    }

    if (t == 0) {
        atomicAdd(&g_sumsq, red[0]);
        __threadfence();
        int c = atomicAdd(&g_fin_count, 1);
        is_last = (c == (W / 2 - 1));
    }
    __syncthreads();
    if (is_last) {
        g_musum[t] = 0.0f;             // reset column stats for next replay
        g_sqsum[t] = 0.0f;
        if (t == 0) {
            float total = atomicAdd(&g_sumsq, 0.0f);   // coherent read
            out[0] = sqrtf(total);
            g_sumsq = 0.0f;
            g_fin_count = 0;
        }
    }
}

// ---------------------------------------------------------------------------
extern "C" void kernel_launch(void* const* d_in, const int* in_sizes, int n_in,
                              void* d_out, int out_size) {
    const float* E = (const float*)d_in[0];   // [8192, 256] fp32
    float* out = (float*)d_out;

    gram_kernel<<<GRID, 256>>>(E);
    finalize_kernel<<<W / 2, 256>>>(out);
}

// round 17
// speedup vs baseline: 2.4646x; 1.1044x over previous
#include <cuda_runtime.h>
#include <math.h>

#define BATCH 8192
#define W 256
#define NKCH 64
#define KCHUNK (BATCH / NKCH)        // 128
#define NPAIR 3                      // 128x128 tile-pairs: (0,0),(0,1),(1,1)
#define GRID (NPAIR * NKCH)          // 192
#define FGRID 192                    // finalize blocks (49152 entries / 256)

// Device scratch (no allocations). Split Gram buffers are fully overwritten
// each launch (no zeroing needed); counters self-reset in finalize.
__device__ float g_Gs[NKCH][W * W];   // per-chunk Gram partials (16 MB, plain ST)
__device__ float g_musum[W];          // column sums (zero-init .bss, self-reset)
__device__ float g_sqsum[W];          // column sum-of-squares (exact diagonal)
__device__ float g_sumsq;             // ||D||^2 accumulator (self-reset)
__device__ int   g_fin_count;         // completion counter (self-reset)

// ---- helpers ---------------------------------------------------------------
__device__ __forceinline__ unsigned pack_bf16x2(float even, float odd) {
    unsigned r;   // hi = odd-k, lo = even-k (consistent for A and B)
    asm("cvt.rn.bf16x2.f32 %0, %1, %2;" : "=r"(r) : "f"(odd), "f"(even));
    return r;
}
__device__ __forceinline__ void mma_bf16(float* d, const unsigned* a,
                                         unsigned b0, unsigned b1) {
    asm("mma.sync.aligned.m16n8k16.row.col.f32.bf16.bf16.f32 "
        "{%0,%1,%2,%3}, {%4,%5,%6,%7}, {%8,%9}, {%0,%1,%2,%3};"
        : "+f"(d[0]), "+f"(d[1]), "+f"(d[2]), "+f"(d[3])
        : "r"(a[0]), "r"(a[1]), "r"(a[2]), "r"(a[3]), "r"(b0), "r"(b1));
}

// ---------------------------------------------------------------------------
// K1: Gram via bf16 MMA on 128x128 symmetric tile-pairs + fused column stats.
// Grid 192 = 3 pairs x 64 K-chunks; 256 threads = 8 warps, warp tile 32x64.
// Each block STORES its partial tile to g_Gs[chunk] (no atomics).
// ---------------------------------------------------------------------------
__global__ __launch_bounds__(256) void gram_kernel(const float* __restrict__ E) {
    __shared__ unsigned As2[16][136];  // k-pairs packed bf16x2; pad 136 conflict-free
    __shared__ unsigned Bs2[16][136];
    __shared__ float s_sum[128];
    __shared__ float s_sq[128];

    const int tid   = threadIdx.x;
    const int pair  = blockIdx.x / NKCH;         // 0:(0,0) 1:(0,1) 2:(1,1)
    const int chunk = blockIdx.x % NKCH;
    const int i0 = (pair == 2) ? 128 : 0;
    const int j0 = (pair == 0) ? 0 : 128;
    const int k0 = chunk * KCHUNK;
    const bool diag = (i0 == j0);

    const int w    = tid >> 5;
    const int lane = tid & 31;
    const int gid  = lane >> 2;       // 0..7
    const int tig  = lane & 3;        // 0..3
    const int iw   = (w >> 1) * 32;   // 4 m-bands of 32
    const int jw   = (w & 1) * 64;    // 2 n-bands of 64

    float acc[2][8][4];
    #pragma unroll
    for (int m = 0; m < 2; ++m)
        #pragma unroll
        for (int n = 0; n < 8; ++n)
            #pragma unroll
            for (int c = 0; c < 4; ++c) acc[m][n][c] = 0.0f;

    float4 csum = make_float4(0.f, 0.f, 0.f, 0.f);
    float4 csq  = make_float4(0.f, 0.f, 0.f, 0.f);
    if (tid < 128) { s_sum[tid] = 0.0f; s_sq[tid] = 0.0f; }

    const int f  = tid & 31;          // float4 col index (128 cols = 32 float4)
    const int rp = tid >> 5;          // 0..7

    for (int kc = 0; kc < KCHUNK; kc += 32) {
        // Stage 32 rows x 128 cols as packed bf16x2 pairs along k.
        #pragma unroll
        for (int q = 0; q < 2; ++q) {
            int k2 = q * 8 + rp;                        // 0..15
            size_t base = (size_t)(k0 + kc + 2 * k2) * W;
            float4 a0 = ((const float4*)(E + base + i0))[f];
            float4 a1 = ((const float4*)(E + base + W + i0))[f];
            uint4 pa = make_uint4(pack_bf16x2(a0.x, a1.x), pack_bf16x2(a0.y, a1.y),
                                  pack_bf16x2(a0.z, a1.z), pack_bf16x2(a0.w, a1.w));
            *(uint4*)&As2[k2][f * 4] = pa;
            if (diag) {
                csum.x += a0.x + a1.x;
                csum.y += a0.y + a1.y;
                csum.z += a0.z + a1.z;
                csum.w += a0.w + a1.w;
                csq.x = fmaf(a0.x, a0.x, fmaf(a1.x, a1.x, csq.x));
                csq.y = fmaf(a0.y, a0.y, fmaf(a1.y, a1.y, csq.y));
                csq.z = fmaf(a0.z, a0.z, fmaf(a1.z, a1.z, csq.z));
                csq.w = fmaf(a0.w, a0.w, fmaf(a1.w, a1.w, csq.w));
            } else {
                float4 b0 = ((const float4*)(E + base + j0))[f];
                float4 b1 = ((const float4*)(E + base + W + j0))[f];
                uint4 pb = make_uint4(pack_bf16x2(b0.x, b1.x), pack_bf16x2(b0.y, b1.y),
                                      pack_bf16x2(b0.z, b1.z), pack_bf16x2(b0.w, b1.w));
                *(uint4*)&Bs2[k2][f * 4] = pb;
            }
        }
        __syncthreads();

        const unsigned (*Bp)[136] = diag ? As2 : Bs2;

        #pragma unroll
        for (int kb2 = 0; kb2 < 16; kb2 += 8) {         // two k16 steps
            unsigned a[2][4];
            #pragma unroll
            for (int m = 0; m < 2; ++m) {
                int mi = iw + m * 16;
                a[m][0] = As2[kb2 + tig    ][mi + gid    ];
                a[m][1] = As2[kb2 + tig    ][mi + gid + 8];
                a[m][2] = As2[kb2 + tig + 4][mi + gid    ];
                a[m][3] = As2[kb2 + tig + 4][mi + gid + 8];
            }
            #pragma unroll
            for (int n = 0; n < 8; ++n) {
                unsigned b0 = Bp[kb2 + tig    ][jw + n * 8 + gid];
                unsigned b1 = Bp[kb2 + tig + 4][jw + n * 8 + gid];
                mma_bf16(acc[0][n], a[0], b0, b1);
                mma_bf16(acc[1][n], a[1], b0, b1);
            }
        }
        __syncthreads();
    }

    // Plain stores of the partial tile (disjoint addresses; no atomics).
    float* dst = g_Gs[chunk];
    #pragma unroll
    for (int m = 0; m < 2; ++m) {
        int gi = i0 + iw + m * 16 + gid;
        #pragma unroll
        for (int n = 0; n < 8; ++n) {
            int gj = j0 + jw + n * 8 + 2 * tig;
            *(float2*)&dst[gi * W + gj]       = make_float2(acc[m][n][0], acc[m][n][1]);
            *(float2*)&dst[(gi + 8) * W + gj] = make_float2(acc[m][n][2], acc[m][n][3]);
        }
    }

    // Diagonal blocks: flush column stats (tiny atomic traffic).
    if (diag) {
        atomicAdd(&s_sum[f * 4 + 0], csum.x);
        atomicAdd(&s_sum[f * 4 + 1], csum.y);
        atomicAdd(&s_sum[f * 4 + 2], csum.z);
        atomicAdd(&s_sum[f * 4 + 3], csum.w);
        atomicAdd(&s_sq[f * 4 + 0], csq.x);
        atomicAdd(&s_sq[f * 4 + 1], csq.y);
        atomicAdd(&s_sq[f * 4 + 2], csq.z);
        atomicAdd(&s_sq[f * 4 + 3], csq.w);
        __syncthreads();
        if (tid < 128) {
            atomicAdd(&g_musum[i0 + tid], s_sum[tid]);
            atomicAdd(&g_sqsum[i0 + tid], s_sq[tid]);
        }
    }
}

// ---------------------------------------------------------------------------
// K2: finalize over the STORED region (49152 entries), 1 entry per thread.
// 192 blocks x 256 threads, fully coalesced split-sum with 8-way MLP.
//   b < 128 : entry (i=b, j=t), tiles (0,0)+(0,1); weight = (j>=128) ? 2 : 1
//             (tile (0,0) stores both mirrors -> weight 1 sums to 2x off-diag)
//   b >= 128: tile (1,1): i = 128 + 2*(b-128) + (t>>7), j = 128 + (t&127), w=1
// Diagonal entries use the exact fp32 sumsq path. Last block: sqrt + reset.
// ---------------------------------------------------------------------------
__global__ __launch_bounds__(256) void finalize_kernel(float* __restrict__ out) {
    __shared__ float mu[W];
    __shared__ float red[256];
    __shared__ int   is_last;

    const int t = threadIdx.x;
    const int b = blockIdx.x;
    const float invB = 1.0f / BATCH;

    mu[t] = g_musum[t] * invB;
    __syncthreads();

    int i, j;
    float wgt;
    if (b < 128) {
        i = b; j = t;
        wgt = (j >= 128) ? 2.0f : 1.0f;
    } else {
        i = 128 + 2 * (b - 128) + (t >> 7);
        j = 128 + (t & 127);
        wgt = 1.0f;
    }

    // Sum the 64 splits: coalesced, 8 independent accumulators.
    const int off = i * W + j;
    float G0 = 0.f, G1 = 0.f, G2 = 0.f, G3 = 0.f;
    float G4 = 0.f, G5 = 0.f, G6 = 0.f, G7 = 0.f;
    #pragma unroll
    for (int s = 0; s < NKCH; s += 8) {
        G0 += g_Gs[s + 0][off];
        G1 += g_Gs[s + 1][off];
        G2 += g_Gs[s + 2][off];
        G3 += g_Gs[s + 3][off];
        G4 += g_Gs[s + 4][off];
        G5 += g_Gs[s + 5][off];
        G6 += g_Gs[s + 6][off];
        G7 += g_Gs[s + 7][off];
    }
    float G = ((G0 + G1) + (G2 + G3)) + ((G4 + G5) + (G6 + G7));

    float a;
    if (j == i) {
        float d = g_sqsum[i] * invB - mu[i] * mu[i] - 1.0f;   // exact diagonal
        a = d * d;
    } else {
        float d = G * invB - mu[i] * mu[j];
        a = wgt * d * d;
    }

    red[t] = a;
    __syncthreads();
    #pragma unroll
    for (int st = 128; st > 0; st >>= 1) {
        if (t < st) red[t] += red[t + st];
        __syncthreads();
    }

    if (t == 0) {
        atomicAdd(&g_sumsq, red[0]);
        __threadfence();
        int c = atomicAdd(&g_fin_count, 1);
        is_last = (c == FGRID - 1);
    }
    __syncthreads();
    if (is_last) {
        g_musum[t] = 0.0f;             // reset column stats for next replay
        g_sqsum[t] = 0.0f;
        if (t == 0) {
            float total = atomicAdd(&g_sumsq, 0.0f);   // coherent read
            out[0] = sqrtf(total);
            g_sumsq = 0.0f;
            g_fin_count = 0;
        }
    }
}

// ---------------------------------------------------------------------------
extern "C" void kernel_launch(void* const* d_in, const int* in_sizes, int n_in,
                              void* d_out, int out_size) {
    const float* E = (const float*)d_in[0];   // [8192, 256] fp32
    float* out = (float*)d_out;

    gram_kernel<<<GRID, 256>>>(E);
    finalize_kernel<<<FGRID, 256>>>(out);
}